// round 2
// baseline (speedup 1.0000x reference)
#include <cuda_runtime.h>
#include <math.h>

#define D 128
#define MAXN 100000
#define MAXE 600000
#define BM 64
#define LTHREADS 256
#define APAD 4
#define ASTRIDE (2 * D + APAD)   // 260 floats

typedef unsigned long long ull;

// ---------------- static device scratch (no allocs allowed) ----------------
__device__ float g_h0[(size_t)MAXN * D];
__device__ float g_h1[(size_t)MAXN * D];
__device__ int   g_cnt[MAXN];
__device__ int   g_off[MAXN + 1];
__device__ int   g_cur[MAXN];
__device__ int   g_src[MAXE];

// ---------------- packed f32x2 helpers (Blackwell FFMA2) ----------------
__device__ __forceinline__ ull fma2(ull a, ull b, ull c) {
    ull d;
    asm("fma.rn.f32x2 %0, %1, %2, %3;" : "=l"(d) : "l"(a), "l"(b), "l"(c));
    return d;
}
__device__ __forceinline__ ull bcast2(float a) {
    ull d; unsigned int ai = __float_as_uint(a);
    asm("mov.b64 %0, {%1, %2};" : "=l"(d) : "r"(ai), "r"(ai));
    return d;
}
__device__ __forceinline__ void unpack2(ull v, float& lo, float& hi) {
    unsigned int l, h;
    asm("mov.b64 {%0, %1}, %2;" : "=r"(l), "=r"(h) : "l"(v));
    lo = __uint_as_float(l); hi = __uint_as_float(h);
}

// ---------------- CSR construction ----------------
__global__ void zero_cnt_kernel(int* cnt, int N) {
    int i = blockIdx.x * blockDim.x + threadIdx.x;
    if (i < N) cnt[i] = 0;
}

__global__ void count_kernel(const int* __restrict__ dst, int* cnt, int E) {
    int e = blockIdx.x * blockDim.x + threadIdx.x;
    if (e < E) atomicAdd(&cnt[dst[e]], 1);
}

// single-block exclusive scan over N counts -> off, cursor
__global__ void scan_kernel(const int* __restrict__ cnt, int* off, int* cur, int N) {
    __shared__ int part[1024];
    int t = threadIdx.x;
    int chunk = (N + 1023) / 1024;
    int s = t * chunk;
    int e = min(s + chunk, N);
    int sum = 0;
    for (int i = s; i < e; ++i) sum += cnt[i];
    part[t] = sum;
    __syncthreads();
    for (int d = 1; d < 1024; d <<= 1) {
        int v = (t >= d) ? part[t - d] : 0;
        __syncthreads();
        part[t] += v;
        __syncthreads();
    }
    int run = (t == 0) ? 0 : part[t - 1];
    for (int i = s; i < e; ++i) {
        off[i] = run;
        cur[i] = run;
        run += cnt[i];
    }
    if (t == 1023) off[N] = part[1023];
}

__global__ void fill_kernel(const int* __restrict__ src, const int* __restrict__ dst,
                            int* cur, int* out, int E) {
    int e = blockIdx.x * blockDim.x + threadIdx.x;
    if (e < E) {
        int d = dst[e];
        int pos = atomicAdd(&cur[d], 1);
        out[pos] = src[e];
    }
}

// ---------------- fused SAGE layer: aggregate + unified GEMM + bias + relu ----
// A[r] = [ mean_nbrs(h)[v] (cols 0..127) | h[v] (cols 128..255) ]
// C[v,:] = relu( A @ [Wl;Wr] + b )
__global__ __launch_bounds__(LTHREADS) void layer_kernel(
    const float* __restrict__ h_in, float* __restrict__ h_out,
    const float* __restrict__ Wl, const float* __restrict__ Wr,
    const float* __restrict__ bias,
    const int* __restrict__ off, const int* __restrict__ srcs, int N)
{
    extern __shared__ float As[];   // [BM][ASTRIDE]

    const int t = threadIdx.x;
    const int lane = t & 31, warp = t >> 5;
    const int row0 = blockIdx.x * BM;

    // ---- stage own rows into cols [128, 256) (coalesced) ----
    for (int i = t; i < BM * (D / 4); i += LTHREADS) {
        int r = i >> 5;
        int c4 = (i & 31) << 2;
        float4 v = make_float4(0.f, 0.f, 0.f, 0.f);
        if (row0 + r < N)
            v = *(const float4*)(h_in + (size_t)(row0 + r) * D + c4);
        *(float4*)&As[r * ASTRIDE + D + c4] = v;
    }

    // ---- CSR gather + mean into cols [0, 128): warp per row group, MLP-4 unrolled ----
    for (int j = 0; j < BM / 8; ++j) {
        int r = warp * 8 + j;
        int v = row0 + r;
        float4 acc = make_float4(0.f, 0.f, 0.f, 0.f);
        if (v < N) {
            int s = off[v];
            int e = off[v + 1];
            int k = s;
            for (; k + 4 <= e; k += 4) {
                int u0 = __ldg(&srcs[k]);
                int u1 = __ldg(&srcs[k + 1]);
                int u2 = __ldg(&srcs[k + 2]);
                int u3 = __ldg(&srcs[k + 3]);
                float4 a = __ldg((const float4*)(h_in + (size_t)u0 * D + lane * 4));
                float4 b = __ldg((const float4*)(h_in + (size_t)u1 * D + lane * 4));
                float4 c = __ldg((const float4*)(h_in + (size_t)u2 * D + lane * 4));
                float4 d = __ldg((const float4*)(h_in + (size_t)u3 * D + lane * 4));
                acc.x += (a.x + b.x) + (c.x + d.x);
                acc.y += (a.y + b.y) + (c.y + d.y);
                acc.z += (a.z + b.z) + (c.z + d.z);
                acc.w += (a.w + b.w) + (c.w + d.w);
            }
            for (; k < e; ++k) {
                int u = __ldg(&srcs[k]);
                float4 a = __ldg((const float4*)(h_in + (size_t)u * D + lane * 4));
                acc.x += a.x; acc.y += a.y; acc.z += a.z; acc.w += a.w;
            }
            float ic = 1.0f / (float)max(e - s, 1);
            acc.x *= ic; acc.y *= ic; acc.z *= ic; acc.w *= ic;
        }
        *(float4*)&As[r * ASTRIDE + lane * 4] = acc;
    }
    __syncthreads();

    // ---- unified GEMM: thread (tr4, tc) -> rows [tr4, tr4+4) x cols [tc*8, tc*8+8) ----
    const int tc  = t & 15;
    const int tr4 = (t >> 4) << 2;

    ull acc[4][4];
#pragma unroll
    for (int i = 0; i < 4; ++i)
#pragma unroll
        for (int j = 0; j < 4; ++j) acc[i][j] = 0ull;

#pragma unroll 1
    for (int pass = 0; pass < 2; ++pass) {
        const ull* W = (const ull*)(pass ? Wr : Wl);
        const float* Ab = As + pass * D;   // col offset 0 (mean) or 128 (own)

#pragma unroll 4
        for (int k = 0; k < D; ++k) {
            int base = (k * D + tc * 8) >> 1;
            ulonglong2 w01 = __ldg((const ulonglong2*)(W + base));
            ulonglong2 w23 = __ldg((const ulonglong2*)(W + base + 2));
            ull w[4] = {w01.x, w01.y, w23.x, w23.y};

            ull a[4];
#pragma unroll
            for (int i = 0; i < 4; ++i)
                a[i] = bcast2(Ab[(tr4 + i) * ASTRIDE + k]);

#pragma unroll
            for (int i = 0; i < 4; ++i)
#pragma unroll
                for (int j = 0; j < 4; ++j)
                    acc[i][j] = fma2(a[i], w[j], acc[i][j]);
        }
    }

    // ---- epilogue: bias + relu + store ----
    float4 b0 = __ldg((const float4*)(bias + tc * 8));
    float4 b1 = __ldg((const float4*)(bias + tc * 8 + 4));
    float bl[8] = {b0.x, b0.y, b0.z, b0.w, b1.x, b1.y, b1.z, b1.w};

#pragma unroll
    for (int i = 0; i < 4; ++i) {
        int gr = row0 + tr4 + i;
        if (gr >= N) continue;
        float o[8];
#pragma unroll
        for (int j = 0; j < 4; ++j) unpack2(acc[i][j], o[2 * j], o[2 * j + 1]);
#pragma unroll
        for (int c = 0; c < 8; ++c) o[c] = fmaxf(o[c] + bl[c], 0.0f);
        float* outp = h_out + (size_t)gr * D + tc * 8;
        *(float4*)(outp)     = make_float4(o[0], o[1], o[2], o[3]);
        *(float4*)(outp + 4) = make_float4(o[4], o[5], o[6], o[7]);
    }
}

// ---------------- pooled sum (sorted batch, binary-search bounds) + sigmoid head ----
__global__ void pool_head_kernel(const float* __restrict__ h, const int* __restrict__ batch,
                                 const float* __restrict__ Wro, const float* __restrict__ bro,
                                 float* __restrict__ out, int N)
{
    __shared__ int bounds[2];
    __shared__ float red[4];
    int g = blockIdx.x;
    int t = threadIdx.x;   // 128 threads, t = feature column

    if (t < 2) {
        int target = g + t;
        int lo = 0, hi = N;
        while (lo < hi) {
            int mid = (lo + hi) >> 1;
            if (batch[mid] < target) lo = mid + 1; else hi = mid;
        }
        bounds[t] = lo;
    }
    __syncthreads();
    int s = bounds[0], e = bounds[1];

    float sum = 0.0f;
    for (int v = s; v < e; ++v) sum += h[(size_t)v * D + t];
    float val = sum * __ldg(&Wro[t]);
#pragma unroll
    for (int o = 16; o > 0; o >>= 1) val += __shfl_xor_sync(0xffffffff, val, o);
    if ((t & 31) == 0) red[t >> 5] = val;
    __syncthreads();
    if (t == 0) {
        float z = red[0] + red[1] + red[2] + red[3] + __ldg(bro);
        out[g] = 1.0f / (1.0f + expf(-z));
    }
}

// ---------------- launcher ----------------
extern "C" void kernel_launch(void* const* d_in, const int* in_sizes, int n_in,
                              void* d_out, int out_size)
{
    const float* x     = (const float*)d_in[0];
    const int*   ei    = (const int*)d_in[1];
    const int*   batch = (const int*)d_in[2];
    const float* Wl1 = (const float*)d_in[3];
    const float* Wr1 = (const float*)d_in[4];
    const float* b1  = (const float*)d_in[5];
    const float* Wl2 = (const float*)d_in[6];
    const float* Wr2 = (const float*)d_in[7];
    const float* b2  = (const float*)d_in[8];
    const float* Wl3 = (const float*)d_in[9];
    const float* Wr3 = (const float*)d_in[10];
    const float* b3  = (const float*)d_in[11];
    const float* Wro = (const float*)d_in[12];
    const float* bro = (const float*)d_in[13];
    float* out = (float*)d_out;

    int N = in_sizes[0] / D;
    int E = in_sizes[1] / 2;
    int G = out_size;

    float *h0, *h1;
    int *cnt, *off, *cur, *srcs;
    cudaGetSymbolAddress((void**)&h0,   g_h0);
    cudaGetSymbolAddress((void**)&h1,   g_h1);
    cudaGetSymbolAddress((void**)&cnt,  g_cnt);
    cudaGetSymbolAddress((void**)&off,  g_off);
    cudaGetSymbolAddress((void**)&cur,  g_cur);
    cudaGetSymbolAddress((void**)&srcs, g_src);

    const int* src_arr = ei;
    const int* dst_arr = ei + E;

    // CSR build
    zero_cnt_kernel<<<(N + 255) / 256, 256>>>(cnt, N);
    count_kernel<<<(E + 255) / 256, 256>>>(dst_arr, cnt, E);
    scan_kernel<<<1, 1024>>>(cnt, off, cur, N);
    fill_kernel<<<(E + 255) / 256, 256>>>(src_arr, dst_arr, cur, srcs, E);

    // fused SAGE layers
    int smem = BM * ASTRIDE * sizeof(float);
    cudaFuncSetAttribute((const void*)layer_kernel,
                         cudaFuncAttributeMaxDynamicSharedMemorySize, smem);
    int lblocks = (N + BM - 1) / BM;
    layer_kernel<<<lblocks, LTHREADS, smem>>>(x,  h0, Wl1, Wr1, b1, off, srcs, N);
    layer_kernel<<<lblocks, LTHREADS, smem>>>(h0, h1, Wl2, Wr2, b2, off, srcs, N);
    layer_kernel<<<lblocks, LTHREADS, smem>>>(h1, h0, Wl3, Wr3, b3, off, srcs, N);

    // pooling + head
    pool_head_kernel<<<G, D>>>(h0, batch, Wro, bro, out, N);
}